// round 3
// baseline (speedup 1.0000x reference)
#include <cuda_runtime.h>

// ---------------------------------------------------------------------------
// PyramidAttention (UrbanODE core), B=32, C=64, H=W=32, 5 scales, N=3278.
//
// Restructured math:
//   S[m,q]      = sum_c refm[c,m] * match[c,q]              (K=32 GEMM)
//   logit[n,p]  = 10*invnorm[n] * sum_d S[n+d, p+d]         (9-tap diag stencil)
//   yn          = softmax over n (per (b,p))
//   T[p,m]      = sum_d yn[m+d, p+d]                        (same stencil)
//   out[c,p]    = x[c,p] + 0.25 * sum_m base[c,m] * T[p,m]  (K=3278 GEMM)
//
// R2 fix: device-global scratch must be referenced from DEVICE code only.
// Passing g_refm/g_base as host-side kernel args took the host shadow address,
// so the pyramid projections were never written (fold term == 0, rel_err 0.26).
// ---------------------------------------------------------------------------

namespace {
constexpr int kB  = 32;
constexpr int kC  = 64;
constexpr int kC2 = 32;
constexpr int kHW = 1024;
constexpr int kN  = 3278;   // 1024+784+625+484+361
constexpr int kNS = 3280;   // padded row stride
}

// scratch (device globals: allocation-free rule)
__device__ float  g_match[(size_t)kB * kC2 * kHW];
__device__ float  g_refm [(size_t)kB * kC2 * kN];
__device__ float  g_base [(size_t)kB * kC  * kN];
__device__ float  g_sq   [(size_t)kB * kN];
__device__ float  g_invn [(size_t)kB * kN];
__device__ float2 g_stats[(size_t)kB * kHW];
__device__ float  g_buf1 [(size_t)kB * kHW * kNS];  // S, later yn
__device__ float  g_buf2 [(size_t)kB * kHW * kNS];  // logits, later T

// pyramid pixel -> (level-local y, x, level width). levels are square.
__device__ __forceinline__ void n_geom(int n, int& ny, int& nx, int& wl)
{
    if (n < 1024)      { int loc = n;        ny = loc >> 5;  nx = loc & 31;     wl = 32; }
    else if (n < 1808) { int loc = n - 1024; ny = loc / 28;  nx = loc - ny*28;  wl = 28; }
    else if (n < 2433) { int loc = n - 1808; ny = loc / 25;  nx = loc - ny*25;  wl = 25; }
    else if (n < 2917) { int loc = n - 2433; ny = loc / 22;  nx = loc - ny*22;  wl = 22; }
    else               { int loc = n - 2917; ny = loc / 19;  nx = loc - ny*19;  wl = 19; }
}

// ---------------------------------------------------------------------------
// match_base = prelu(conv1x1(x, w_base)) : [B,32,1024]
// ---------------------------------------------------------------------------
__global__ __launch_bounds__(256) void k_conv_main(
    const float* __restrict__ x, const float* __restrict__ w,
    const float* __restrict__ bias, const float* __restrict__ a)
{
    int t = blockIdx.x * blockDim.x + threadIdx.x;
    if (t >= kB * kC2 * kHW) return;
    int p  = t & (kHW - 1);
    int co = (t >> 10) & 31;
    int b  = t >> 15;
    const float* xb = x + ((size_t)b * kC) * kHW + p;
    const float* wr = w + co * kC;
    float acc = bias[co];
#pragma unroll
    for (int c = 0; c < kC; c++) acc = fmaf(wr[c], xb[(size_t)c * kHW], acc);
    float al = a[0];
    g_match[t] = acc >= 0.f ? acc : al * acc;
}

// ---------------------------------------------------------------------------
// pyramid conv1x1 + prelu on nearest-resized x (resize folded into indexing).
// DST selects the destination device global INSIDE device code (R2 fix).
// ---------------------------------------------------------------------------
template <int COUT, int DST>
__global__ __launch_bounds__(256) void k_conv_pyr(
    const float* __restrict__ x, const float* __restrict__ w,
    const float* __restrict__ bias, const float* __restrict__ a)
{
    __shared__ float ws[COUT * kC];
    for (int i = threadIdx.x; i < COUT * kC; i += 256) ws[i] = w[i];
    __syncthreads();

    int n = blockIdx.x * 256 + threadIdx.x;
    int b = blockIdx.y;
    if (n >= kN) return;

    int ny, nx, wl;
    n_geom(n, ny, nx, wl);
    int sy = (ny * 32) / wl;      // nearest, recompute_scale_factor semantics
    int sx = (nx * 32) / wl;
    const float* xb = x + ((size_t)b * kC) * kHW + sy * 32 + sx;

    float acc[COUT];
#pragma unroll
    for (int co = 0; co < COUT; co++) acc[co] = bias[co];
#pragma unroll 4
    for (int c = 0; c < kC; c++) {
        float xv = xb[(size_t)c * kHW];
#pragma unroll
        for (int co = 0; co < COUT; co++) acc[co] = fmaf(ws[co * kC + c], xv, acc[co]);
    }
    float al = a[0];
    float* ob = (DST == 0 ? g_refm : g_base) + (size_t)b * COUT * kN + n;
#pragma unroll
    for (int co = 0; co < COUT; co++) {
        float v = acc[co];
        ob[(size_t)co * kN] = v >= 0.f ? v : al * v;
    }
}

// per-pixel sum of refm^2 over channels
__global__ __launch_bounds__(256) void k_sq()
{
    int t = blockIdx.x * blockDim.x + threadIdx.x;
    if (t >= kB * kN) return;
    int n = t % kN, b = t / kN;
    const float* rf = g_refm + (size_t)b * kC2 * kN + n;
    float s = 0.f;
#pragma unroll
    for (int c = 0; c < kC2; c++) { float v = rf[(size_t)c * kN]; s = fmaf(v, v, s); }
    g_sq[t] = s;
}

// invnorm[n] = 10 / max(sqrt(sum_{valid d} sq[n+d]), 1e-4)
__global__ __launch_bounds__(256) void k_invn()
{
    int t = blockIdx.x * blockDim.x + threadIdx.x;
    if (t >= kB * kN) return;
    int n = t % kN, b = t / kN;
    int ny, nx, wl;
    n_geom(n, ny, nx, wl);
    const float* sq = g_sq + (size_t)b * kN;
    float s = 0.f;
#pragma unroll
    for (int dy = -1; dy <= 1; dy++) {
        int my = ny + dy;
        if ((unsigned)my >= (unsigned)wl) continue;
#pragma unroll
        for (int dx = -1; dx <= 1; dx++) {
            int mx = nx + dx;
            if ((unsigned)mx >= (unsigned)wl) continue;
            s += sq[n + dy * wl + dx];
        }
    }
    float nr = fmaxf(sqrtf(s), 1e-4f);
    g_invn[t] = 10.f / nr;
}

// ---------------------------------------------------------------------------
// GEMM1: S[b][p][n] = sum_{c<32} match[b][c][p] * refm[b][c][n]
// ---------------------------------------------------------------------------
__global__ __launch_bounds__(256) void k_gemm1()
{
    __shared__ float As[32][65];  // [k][p]
    __shared__ float Bs[32][65];  // [k][n]
    int b  = blockIdx.z;
    int p0 = blockIdx.y * 64;
    int n0 = blockIdx.x * 64;
    const float* Ab = g_match + (size_t)b * kC2 * kHW;
    const float* Bb = g_refm  + (size_t)b * kC2 * kN;
    int tid = threadIdx.x;
#pragma unroll
    for (int i = tid; i < 32 * 64; i += 256) {
        int k = i >> 6, j = i & 63;
        As[k][j] = Ab[(size_t)k * kHW + p0 + j];
        int n = n0 + j;
        Bs[k][j] = (n < kN) ? Bb[(size_t)k * kN + n] : 0.f;
    }
    __syncthreads();
    int tx = tid & 15, ty = tid >> 4;
    float acc[4][4] = {};
#pragma unroll
    for (int k = 0; k < 32; k++) {
        float av[4], bv[4];
#pragma unroll
        for (int r = 0; r < 4; r++) av[r] = As[k][ty + r * 16];
#pragma unroll
        for (int l = 0; l < 4; l++) bv[l] = Bs[k][tx + l * 16];
#pragma unroll
        for (int r = 0; r < 4; r++)
#pragma unroll
            for (int l = 0; l < 4; l++) acc[r][l] = fmaf(av[r], bv[l], acc[r][l]);
    }
    float* Sb = g_buf1 + (size_t)b * kHW * kNS;
#pragma unroll
    for (int r = 0; r < 4; r++) {
        int p = p0 + ty + r * 16;
#pragma unroll
        for (int l = 0; l < 4; l++) {
            int n = n0 + tx + l * 16;
            if (n < kN) Sb[(size_t)p * kNS + n] = acc[r][l];
        }
    }
}

// ---------------------------------------------------------------------------
// diagonal 9-tap stencil: dst[b][p][n] = sum_{valid d} src[b][p+d][n+d]
// SCALE=true multiplies by invnorm (logits); SCALE=false is the T stencil.
// ---------------------------------------------------------------------------
template <bool SCALE>
__global__ __launch_bounds__(256) void k_stencil()
{
    int n = blockIdx.x * 256 + threadIdx.x;
    if (n >= kN) return;
    int p = blockIdx.y, b = blockIdx.z;
    int ny, nx, wl;
    n_geom(n, ny, nx, wl);
    int py = p >> 5, px = p & 31;
    const float* S = g_buf1 + (size_t)b * kHW * kNS;
    float s = 0.f;
#pragma unroll
    for (int dy = -1; dy <= 1; dy++) {
        int qy = py + dy, my = ny + dy;
        if ((unsigned)qy >= 32u || (unsigned)my >= (unsigned)wl) continue;
#pragma unroll
        for (int dx = -1; dx <= 1; dx++) {
            int qx = px + dx, mx = nx + dx;
            if ((unsigned)qx >= 32u || (unsigned)mx >= (unsigned)wl) continue;
            s += S[(size_t)(qy * 32 + qx) * kNS + (n + dy * wl + dx)];
        }
    }
    if (SCALE) s *= g_invn[(size_t)b * kN + n];
    g_buf2[((size_t)b * kHW + p) * kNS + n] = s;
}

// ---------------------------------------------------------------------------
// softmax stats per (b,p): row max + 1/sum(exp)
// ---------------------------------------------------------------------------
__global__ __launch_bounds__(256) void k_stats()
{
    __shared__ float sd[kNS];
    __shared__ float red[256];
    int p = blockIdx.x, b = blockIdx.y, tid = threadIdx.x;
    const float* row = g_buf2 + ((size_t)b * kHW + p) * kNS;
    float mx = -3.4e38f;
    for (int n = tid; n < kN; n += 256) {
        float v = row[n];
        sd[n] = v;
        mx = fmaxf(mx, v);
    }
    red[tid] = mx;
    __syncthreads();
#pragma unroll
    for (int s = 128; s > 0; s >>= 1) {
        if (tid < s) red[tid] = fmaxf(red[tid], red[tid + s]);
        __syncthreads();
    }
    mx = red[0];
    __syncthreads();
    float sum = 0.f;
    for (int n = tid; n < kN; n += 256) sum += __expf(sd[n] - mx);
    red[tid] = sum;
    __syncthreads();
#pragma unroll
    for (int s = 128; s > 0; s >>= 1) {
        if (tid < s) red[tid] += red[tid + s];
        __syncthreads();
    }
    if (tid == 0) g_stats[(size_t)b * kHW + p] = make_float2(mx, 1.f / red[0]);
}

// yn = exp(logit - max) * invsum   (buf2 -> buf1)
__global__ __launch_bounds__(256) void k_expnorm()
{
    int n = blockIdx.x * 256 + threadIdx.x;
    if (n >= kN) return;
    int p = blockIdx.y, b = blockIdx.z;
    size_t ro = ((size_t)b * kHW + p) * kNS;
    float2 st = g_stats[(size_t)b * kHW + p];
    g_buf1[ro + n] = __expf(g_buf2[ro + n] - st.x) * st.y;
}

// ---------------------------------------------------------------------------
// GEMM2 + epilogue: out[b][c][p] = x[b][c][p] + 0.25 * sum_m base[b][c][m]*T[b][p][m]
// ---------------------------------------------------------------------------
__global__ __launch_bounds__(256) void k_gemm2(
    const float* __restrict__ x, float* __restrict__ out)
{
    constexpr int BK = 32;
    __shared__ float As[BK][65];    // [k][c]
    __shared__ float Bs[BK][133];   // [k][p]
    int b  = blockIdx.y;
    int p0 = blockIdx.x * 128;
    const float* Ab = g_base + (size_t)b * kC * kN;
    const float* Tb = g_buf2 + (size_t)b * kHW * kNS;
    int tid = threadIdx.x;
    int tx = tid & 31, ty = tid >> 5;
    float acc[8][4] = {};

    for (int k0 = 0; k0 < kN; k0 += BK) {
#pragma unroll
        for (int i = tid; i < 64 * BK; i += 256) {
            int c = i >> 5, kk = i & 31;
            int k = k0 + kk;
            As[kk][c] = (k < kN) ? Ab[(size_t)c * kN + k] : 0.f;
        }
#pragma unroll
        for (int i = tid; i < 128 * BK; i += 256) {
            int pp = i >> 5, kk = i & 31;
            int k = k0 + kk;
            Bs[kk][pp] = (k < kN) ? Tb[(size_t)(p0 + pp) * kNS + k] : 0.f;
        }
        __syncthreads();
#pragma unroll
        for (int k = 0; k < BK; k++) {
            float av[8], bv[4];
#pragma unroll
            for (int r = 0; r < 8; r++) av[r] = As[k][ty + r * 8];
#pragma unroll
            for (int l = 0; l < 4; l++) bv[l] = Bs[k][tx + l * 32];
#pragma unroll
            for (int r = 0; r < 8; r++)
#pragma unroll
                for (int l = 0; l < 4; l++) acc[r][l] = fmaf(av[r], bv[l], acc[r][l]);
        }
        __syncthreads();
    }

    const float* xb = x   + (size_t)b * kC * kHW;
    float*       ob = out + (size_t)b * kC * kHW;
#pragma unroll
    for (int r = 0; r < 8; r++) {
        int c = ty + r * 8;
#pragma unroll
        for (int l = 0; l < 4; l++) {
            int p = p0 + tx + l * 32;
            ob[(size_t)c * kHW + p] = fmaf(0.25f, acc[r][l], xb[(size_t)c * kHW + p]);
        }
    }
}

// ---------------------------------------------------------------------------
extern "C" void kernel_launch(void* const* d_in, const int* in_sizes, int n_in,
                              void* d_out, int out_size)
{
    (void)in_sizes; (void)n_in; (void)out_size;
    const float* x       = (const float*)d_in[0];
    const float* w_base  = (const float*)d_in[1];
    const float* b_base  = (const float*)d_in[2];
    const float* a_base  = (const float*)d_in[3];
    const float* w_match = (const float*)d_in[4];
    const float* b_match = (const float*)d_in[5];
    const float* a_match = (const float*)d_in[6];
    const float* w_asm   = (const float*)d_in[7];
    const float* b_asm   = (const float*)d_in[8];
    const float* a_asm   = (const float*)d_in[9];
    float* out = (float*)d_out;

    // 1) projections
    k_conv_main<<<(kB * kC2 * kHW + 255) / 256, 256>>>(x, w_base, b_base, a_base);
    {
        dim3 g((kN + 255) / 256, kB);
        k_conv_pyr<kC2, 0><<<g, 256>>>(x, w_match, b_match, a_match);  // -> g_refm
        k_conv_pyr<kC,  1><<<g, 256>>>(x, w_asm,   b_asm,   a_asm);    // -> g_base
    }
    // 2) filter norms
    k_sq  <<<(kB * kN + 255) / 256, 256>>>();
    k_invn<<<(kB * kN + 255) / 256, 256>>>();
    // 3) pixel-level correlation S
    {
        dim3 g((kN + 63) / 64, kHW / 64, kB);
        k_gemm1<<<g, 256>>>();
    }
    // 4) logits = 10*invnorm * stencil(S); 5) stats; 6) yn; 7) T
    {
        dim3 g((kN + 255) / 256, kHW, kB);
        k_stencil<true><<<g, 256>>>();
        dim3 gs(kHW, kB);
        k_stats<<<gs, 256>>>();
        k_expnorm<<<g, 256>>>();
        k_stencil<false><<<g, 256>>>();
    }
    // 8) fold GEMM + residual
    {
        dim3 g(kHW / 128, kB);
        k_gemm2<<<g, 256>>>(x, out);
    }
}